// round 6
// baseline (speedup 1.0000x reference)
#include <cuda_runtime.h>

#define B_  16
#define C_  64
#define H_  224
#define W_  224
#define O_  128
#define PH_ 16
#define OH_ 222
#define OW_ 222
#define HW56 (H_ * 56)
#define HB  (B_ / 2)          // batches per half

typedef unsigned long long ull;

__device__ float g_s[(size_t)B_ * H_ * W_];

__device__ __forceinline__ ull mul2(ull a, ull b) {
    ull d; asm("mul.rn.f32x2 %0,%1,%2;" : "=l"(d) : "l"(a), "l"(b)); return d;
}
__device__ __forceinline__ ull fma2(ull a, ull b, ull c) {
    ull d; asm("fma.rn.f32x2 %0,%1,%2,%3;" : "=l"(d) : "l"(a), "l"(b), "l"(c)); return d;
}
__device__ __forceinline__ ull packf2(float lo, float hi) {
    ull d; asm("mov.b64 %0,{%1,%2};" : "=l"(d) : "f"(lo), "f"(hi)); return d;
}

// Streams/events at static init (proven capture-legal in R3).
struct PipeRes {
    cudaStream_t s1;
    cudaEvent_t evA, evB, join;
    PipeRes() {
        cudaStreamCreateWithFlags(&s1, cudaStreamNonBlocking);
        cudaEventCreateWithFlags(&evA, cudaEventDisableTiming);
        cudaEventCreateWithFlags(&evB, cudaEventDisableTiming);
        cudaEventCreateWithFlags(&join, cudaEventDisableTiming);
    }
};
static PipeRes g_pipe;

// ============ Kernel 1: channel reduction ============
// 112 threads: 4 rows x 28 thread-cols, 2 consecutive float4 per thread.
// grid per half = HB * 56 = 448
__global__ __launch_bounds__(112) void k1_reduce(
    const float* __restrict__ x,
    const float* __restrict__ pw,
    const float* __restrict__ pb,
    int b0)
{
    const int blk = blockIdx.x;
    const int b   = b0 + blk / 56;
    const int h0  = (blk % 56) * 4;

    __shared__ float4 bsum[4][4];
    const int t = threadIdx.x;

    if (t < 16) {
        int rr = t >> 2, w4 = t & 3;
        int hh = (h0 + rr) & (PH_ - 1);
        const float4* pb4 = (const float4*)pb;
        float4 s = make_float4(0.f, 0.f, 0.f, 0.f);
        #pragma unroll 16
        for (int c = 0; c < C_; c++) {
            float4 v = __ldg(pb4 + c * 64 + hh * 4 + w4);
            s.x += v.x; s.y += v.y; s.z += v.z; s.w += v.w;
        }
        bsum[rr][w4] = s;
    }
    __syncthreads();

    const int r   = t / 28;
    const int q   = t % 28;
    const int h   = h0 + r;
    const int hh  = h & (PH_ - 1);
    const int f0  = 2 * q;             // first float4 column (0..54, even)
    const int w4a = f0 & 3;            // 0 or 2

    const float4* xp  = (const float4*)x + ((size_t)b * C_ * H_ + h) * 56 + f0;
    const float4* pwp = (const float4*)pw + hh * 4 + w4a;

    float4 acc0 = bsum[r][w4a];
    float4 acc1 = bsum[r][w4a + 1];

    #pragma unroll 8
    for (int c = 0; c < C_; c++) {
        float4 xv0 = __ldg(xp + (size_t)c * HW56);
        float4 xv1 = __ldg(xp + (size_t)c * HW56 + 1);
        float4 wv0 = __ldg(pwp + c * 64);
        float4 wv1 = __ldg(pwp + c * 64 + 1);
        acc0.x = fmaf(xv0.x, wv0.x, acc0.x);
        acc0.y = fmaf(xv0.y, wv0.y, acc0.y);
        acc0.z = fmaf(xv0.z, wv0.z, acc0.z);
        acc0.w = fmaf(xv0.w, wv0.w, acc0.w);
        acc1.x = fmaf(xv1.x, wv1.x, acc1.x);
        acc1.y = fmaf(xv1.y, wv1.y, acc1.y);
        acc1.z = fmaf(xv1.z, wv1.z, acc1.z);
        acc1.w = fmaf(xv1.w, wv1.w, acc1.w);
    }
    float4* sp = (float4*)g_s + ((size_t)b * H_ + h) * 56 + f0;
    sp[0] = acc0;
    sp[1] = acc1;
}

// ============ Kernel 2: 3x3 conv, packed f32x2 ============
// block = 224 threads = 2 output rows x 112 col-pairs; OCG = 32 channels.
// grid per half = (HB * 111, 4)
#define OCG 32
__global__ __launch_bounds__(224) void k2_conv3x3(
    const float* __restrict__ comp,
    float* __restrict__ out,
    int b0)
{
    const int gx = blockIdx.x;
    const int b  = b0 + gx / (OH_ / 2);
    const int i0 = (gx % (OH_ / 2)) * 2;
    const int o0 = blockIdx.y * OCG;

    __shared__ float srow[4][W_];
    __shared__ ulonglong2 wsh[OCG][5];   // 9 weights duplicated into f32 pairs + pad

    const int t = threadIdx.x;

    const float* sp = g_s + ((size_t)b * H_ + i0) * W_;
    #pragma unroll
    for (int k = 0; k < 4; k++)
        srow[k][t] = sp[k * W_ + t];
    for (int idx = t; idx < OCG * 10; idx += 224) {
        int k = idx / 10, m = idx % 10;
        float w = (m < 9) ? comp[(o0 + k) * 9 + m] : 0.f;
        ((float2*)wsh)[idx] = make_float2(w, w);
    }
    __syncthreads();

    const int rp = t / 112;
    const int q  = t % 112;
    if (q >= 111) return;
    const int j0 = q * 2;
    const int i  = i0 + rp;

    // P[d][0..2]: shifted pairs of s row rp+d
    ull P[3][3];
    #pragma unroll
    for (int d = 0; d < 3; d++) {
        float2 lo = *(const float2*)&srow[rp + d][j0];
        float2 hi = *(const float2*)&srow[rp + d][j0 + 2];
        P[d][0] = packf2(lo.x, lo.y);
        P[d][1] = packf2(lo.y, hi.x);
        P[d][2] = packf2(hi.x, hi.y);
    }

    size_t base = (((size_t)b * O_ + o0) * OH_ + i) * OW_ + j0;

    #pragma unroll 8
    for (int k = 0; k < OCG; k++) {
        ulonglong2 w01 = wsh[k][0], w23 = wsh[k][1];
        ulonglong2 w45 = wsh[k][2], w67 = wsh[k][3];
        ulonglong2 w8x = wsh[k][4];

        ull acc = mul2(w01.x, P[0][0]);
        acc = fma2(w01.y, P[0][1], acc);
        acc = fma2(w23.x, P[0][2], acc);
        acc = fma2(w23.y, P[1][0], acc);
        acc = fma2(w45.x, P[1][1], acc);
        acc = fma2(w45.y, P[1][2], acc);
        acc = fma2(w67.x, P[2][0], acc);
        acc = fma2(w67.y, P[2][1], acc);
        acc = fma2(w8x.x, P[2][2], acc);

        *(ull*)(out + base + (size_t)k * (OH_ * OW_)) = acc;
    }
}

extern "C" void kernel_launch(void* const* d_in, const int* in_sizes, int n_in,
                              void* d_out, int out_size)
{
    const float* x    = (const float*)d_in[0];
    const float* pw   = (const float*)d_in[1];
    const float* pb   = (const float*)d_in[2];
    const float* comp = (const float*)d_in[3];
    float* out = (float*)d_out;

    dim3 g1(HB * 56);
    dim3 g2(HB * (OH_ / 2), O_ / OCG);

    // half A produce
    k1_reduce<<<g1, 112>>>(x, pw, pb, 0);
    cudaEventRecord(g_pipe.evA, 0);
    cudaStreamWaitEvent(g_pipe.s1, g_pipe.evA, 0);
    // half A consume (side stream) || half B produce (main stream)
    k2_conv3x3<<<g2, 224, 0, g_pipe.s1>>>(comp, out, 0);
    k1_reduce<<<g1, 112>>>(x, pw, pb, HB);
    cudaEventRecord(g_pipe.evB, 0);
    cudaStreamWaitEvent(g_pipe.s1, g_pipe.evB, 0);
    // half B consume
    k2_conv3x3<<<g2, 224, 0, g_pipe.s1>>>(comp, out, HB);
    cudaEventRecord(g_pipe.join, g_pipe.s1);
    cudaStreamWaitEvent(0, g_pipe.join, 0);
}

// round 7
// speedup vs baseline: 1.3484x; 1.3484x over previous
#include <cuda_runtime.h>

#define B_  16
#define C_  64
#define H_  224
#define W_  224
#define O_  128
#define PH_ 16
#define OH_ 222
#define OW_ 222
#define HW56 (H_ * 56)

__device__ float g_s[(size_t)B_ * H_ * W_];
__device__ float4 g_bsum4[64];   // sum_c pb, as 16 hh x 4 float4-cols

// ---------- k0: bias channel-sum (tiny, 1 block) ----------
__global__ void k0_bias(const float* __restrict__ pb)
{
    const int t = threadIdx.x;   // 0..63
    const float4* pb4 = (const float4*)pb;
    float4 a = make_float4(0.f, 0.f, 0.f, 0.f);
    #pragma unroll 16
    for (int c = 0; c < C_; c++) {
        float4 v = __ldg(pb4 + c * 64 + t);
        a.x += v.x; a.y += v.y; a.z += v.z; a.w += v.w;
    }
    g_bsum4[t] = a;
}

// ---------- k1: channel reduction, flat mapping, forced MLP=8 ----------
// grid = 1568 blocks x 128 threads; thread p handles one float4 of s.
__global__ __launch_bounds__(128, 6) void k1_reduce(
    const float* __restrict__ x,
    const float* __restrict__ pw)
{
    const int p   = blockIdx.x * 128 + threadIdx.x;   // 0 .. 200703
    const int col = p % 56;
    const int bh  = p / 56;
    const int h   = bh % H_;
    const int hh  = h & (PH_ - 1);
    const int w4  = col & 3;

    const float4* xp = (const float4*)x + (size_t)(bh / H_) * C_ * HW56
                                        + (size_t)h * 56 + col;
    const float4* wp = (const float4*)pw + hh * 4 + w4;

    float4 acc = __ldg(&g_bsum4[hh * 4 + w4]);

    #pragma unroll 2
    for (int c0 = 0; c0 < C_; c0 += 8) {
        float4 xv[8];
        #pragma unroll
        for (int j = 0; j < 8; j++)
            xv[j] = __ldg(xp + (size_t)(c0 + j) * HW56);
        #pragma unroll
        for (int j = 0; j < 8; j++) {
            float4 wv = __ldg(wp + (c0 + j) * 64);
            acc.x = fmaf(xv[j].x, wv.x, acc.x);
            acc.y = fmaf(xv[j].y, wv.y, acc.y);
            acc.z = fmaf(xv[j].z, wv.z, acc.z);
            acc.w = fmaf(xv[j].w, wv.w, acc.w);
        }
    }
    ((float4*)g_s)[p] = acc;
}

// ---------- k2: 3x3 conv (byte-identical to R2 winner) ----------
#define OCG 32
__global__ __launch_bounds__(224) void k2_conv3x3(
    const float* __restrict__ comp,
    float* __restrict__ out)
{
    const int gx = blockIdx.x;
    const int b  = gx / (OH_ / 2);
    const int i0 = (gx % (OH_ / 2)) * 2;
    const int o0 = blockIdx.y * OCG;

    __shared__ float srow[4][W_];
    __shared__ float csh[OCG * 12];

    const int t = threadIdx.x;

    const float* sp = g_s + ((size_t)b * H_ + i0) * W_;
    #pragma unroll
    for (int k = 0; k < 4; k++)
        srow[k][t] = sp[k * W_ + t];
    for (int idx = t; idx < OCG * 9; idx += 224) {
        int k = idx / 9, m = idx % 9;
        csh[k * 12 + m] = comp[(o0 + k) * 9 + m];
    }
    __syncthreads();

    const int r  = t / 112;
    const int q  = t % 112;
    if (q >= 111) return;
    const int j0 = q * 2;
    const int i  = i0 + r;

    float2 va[3], vb[3];
    #pragma unroll
    for (int d = 0; d < 3; d++) {
        va[d] = *(const float2*)&srow[r + d][j0];
        vb[d] = *(const float2*)&srow[r + d][j0 + 2];
    }

    const float4* csh4 = (const float4*)csh;
    size_t base = (((size_t)b * O_ + o0) * OH_ + i) * OW_ + j0;

    #pragma unroll 8
    for (int k = 0; k < OCG; k++) {
        float4 w0 = csh4[k * 3 + 0];
        float4 w1 = csh4[k * 3 + 1];
        float4 w2 = csh4[k * 3 + 2];

        float ax, ay;
        ax = w0.x * va[0].x; ay = w0.x * va[0].y;
        ax = fmaf(w0.y, va[0].y, ax); ay = fmaf(w0.y, vb[0].x, ay);
        ax = fmaf(w0.z, vb[0].x, ax); ay = fmaf(w0.z, vb[0].y, ay);

        ax = fmaf(w0.w, va[1].x, ax); ay = fmaf(w0.w, va[1].y, ay);
        ax = fmaf(w1.x, va[1].y, ax); ay = fmaf(w1.x, vb[1].x, ay);
        ax = fmaf(w1.y, vb[1].x, ax); ay = fmaf(w1.y, vb[1].y, ay);

        ax = fmaf(w1.z, va[2].x, ax); ay = fmaf(w1.z, va[2].y, ay);
        ax = fmaf(w1.w, va[2].y, ax); ay = fmaf(w1.w, vb[2].x, ay);
        ax = fmaf(w2.x, vb[2].x, ax); ay = fmaf(w2.x, vb[2].y, ay);

        *(float2*)(out + base + (size_t)k * (OH_ * OW_)) = make_float2(ax, ay);
    }
}

extern "C" void kernel_launch(void* const* d_in, const int* in_sizes, int n_in,
                              void* d_out, int out_size)
{
    const float* x    = (const float*)d_in[0];
    const float* pw   = (const float*)d_in[1];
    const float* pb   = (const float*)d_in[2];
    const float* comp = (const float*)d_in[3];
    float* out = (float*)d_out;

    k0_bias<<<1, 64>>>(pb);
    k1_reduce<<<(B_ * H_ * 56) / 128, 128>>>(x, pw);
    dim3 g2(B_ * (OH_ / 2), O_ / OCG);
    k2_conv3x3<<<g2, 224>>>(comp, out);
}

// round 8
// speedup vs baseline: 1.3811x; 1.0243x over previous
#include <cuda_runtime.h>

#define B_  16
#define C_  64
#define H_  224
#define W_  224
#define O_  128
#define PH_ 16
#define OH_ 222
#define OW_ 222
#define HW56 (H_ * 224 / 4 * 0 + H_ * 56)   // H_*56

__device__ float g_s[(size_t)B_ * H_ * W_];

// ---------- k1: channel reduction, flat mapping, MLP=8, inline bias ----------
// grid = 1568 blocks x 128 threads; thread p handles one float4 of s.
__global__ __launch_bounds__(128, 6) void k1_reduce(
    const float* __restrict__ x,
    const float* __restrict__ pw,
    const float* __restrict__ pb)
{
    __shared__ float4 bs[64];                 // sum_c pb : 16 hh x 4 float4-cols

    const int t = threadIdx.x;
    if (t < 64) {
        const float4* pb4 = (const float4*)pb;
        float4 a = make_float4(0.f, 0.f, 0.f, 0.f);
        #pragma unroll 16
        for (int c = 0; c < C_; c++) {
            float4 v = __ldg(pb4 + c * 64 + t);
            a.x += v.x; a.y += v.y; a.z += v.z; a.w += v.w;
        }
        bs[t] = a;
    }

    const int p   = blockIdx.x * 128 + t;     // 0 .. 200703
    const int col = p % 56;
    const int bh  = p / 56;
    const int h   = bh % H_;
    const int hh  = h & (PH_ - 1);
    const int w4  = col & 3;

    const float4* xp = (const float4*)x + (size_t)(bh / H_) * C_ * HW56
                                        + (size_t)h * 56 + col;
    const float4* wp = (const float4*)pw + hh * 4 + w4;

    __syncthreads();
    float4 acc = bs[hh * 4 + w4];

    #pragma unroll 2
    for (int c0 = 0; c0 < C_; c0 += 8) {
        float4 xv[8];
        #pragma unroll
        for (int j = 0; j < 8; j++)
            xv[j] = __ldg(xp + (size_t)(c0 + j) * HW56);
        #pragma unroll
        for (int j = 0; j < 8; j++) {
            float4 wv = __ldg(wp + (c0 + j) * 64);
            acc.x = fmaf(xv[j].x, wv.x, acc.x);
            acc.y = fmaf(xv[j].y, wv.y, acc.y);
            acc.z = fmaf(xv[j].z, wv.z, acc.z);
            acc.w = fmaf(xv[j].w, wv.w, acc.w);
        }
    }
    ((float4*)g_s)[p] = acc;
}

// ---------- k2: 3x3 conv (byte-identical to proven winner) ----------
#define OCG 32
__global__ __launch_bounds__(224) void k2_conv3x3(
    const float* __restrict__ comp,
    float* __restrict__ out)
{
    const int gx = blockIdx.x;
    const int b  = gx / (OH_ / 2);
    const int i0 = (gx % (OH_ / 2)) * 2;
    const int o0 = blockIdx.y * OCG;

    __shared__ float srow[4][W_];
    __shared__ float csh[OCG * 12];

    const int t = threadIdx.x;

    const float* sp = g_s + ((size_t)b * H_ + i0) * W_;
    #pragma unroll
    for (int k = 0; k < 4; k++)
        srow[k][t] = sp[k * W_ + t];
    for (int idx = t; idx < OCG * 9; idx += 224) {
        int k = idx / 9, m = idx % 9;
        csh[k * 12 + m] = comp[(o0 + k) * 9 + m];
    }
    __syncthreads();

    const int r  = t / 112;
    const int q  = t % 112;
    if (q >= 111) return;
    const int j0 = q * 2;
    const int i  = i0 + r;

    float2 va[3], vb[3];
    #pragma unroll
    for (int d = 0; d < 3; d++) {
        va[d] = *(const float2*)&srow[r + d][j0];
        vb[d] = *(const float2*)&srow[r + d][j0 + 2];
    }

    const float4* csh4 = (const float4*)csh;
    size_t base = (((size_t)b * O_ + o0) * OH_ + i) * OW_ + j0;

    #pragma unroll 8
    for (int k = 0; k < OCG; k++) {
        float4 w0 = csh4[k * 3 + 0];
        float4 w1 = csh4[k * 3 + 1];
        float4 w2 = csh4[k * 3 + 2];

        float ax, ay;
        ax = w0.x * va[0].x; ay = w0.x * va[0].y;
        ax = fmaf(w0.y, va[0].y, ax); ay = fmaf(w0.y, vb[0].x, ay);
        ax = fmaf(w0.z, vb[0].x, ax); ay = fmaf(w0.z, vb[0].y, ay);

        ax = fmaf(w0.w, va[1].x, ax); ay = fmaf(w0.w, va[1].y, ay);
        ax = fmaf(w1.x, va[1].y, ax); ay = fmaf(w1.x, vb[1].x, ay);
        ax = fmaf(w1.y, vb[1].x, ax); ay = fmaf(w1.y, vb[1].y, ay);

        ax = fmaf(w1.z, va[2].x, ax); ay = fmaf(w1.z, va[2].y, ay);
        ax = fmaf(w1.w, va[2].y, ax); ay = fmaf(w1.w, vb[2].x, ay);
        ax = fmaf(w2.x, vb[2].x, ax); ay = fmaf(w2.x, vb[2].y, ay);

        *(float2*)(out + base + (size_t)k * (OH_ * OW_)) = make_float2(ax, ay);
    }
}

extern "C" void kernel_launch(void* const* d_in, const int* in_sizes, int n_in,
                              void* d_out, int out_size)
{
    const float* x    = (const float*)d_in[0];
    const float* pw   = (const float*)d_in[1];
    const float* pb   = (const float*)d_in[2];
    const float* comp = (const float*)d_in[3];
    float* out = (float*)d_out;

    k1_reduce<<<(B_ * H_ * 56) / 128, 128>>>(x, pw, pb);
    dim3 g2(B_ * (OH_ / 2), O_ / OCG);
    k2_conv3x3<<<g2, 224>>>(comp, out);
}